// round 3
// baseline (speedup 1.0000x reference)
#include <cuda_runtime.h>
#include <cuda_bf16.h>

// ---------------------------------------------------------------------------
// SimplifiedMamba2Block: LN -> GEMM1(+clip,split,tanh) -> sequential SSM scan
//                        -> GEMM2(+clip) -> LN
// Shapes: x (4,2048,1024); W_in (3072,1024); W_out (1024,1536);
//         A_log/B/C (1536,8); ln params (1024,)
// ---------------------------------------------------------------------------

#define NTOK   8192          // 4*2048
#define DM     1024
#define DI     1536
#define DS     8
#define NDI2   3072          // 2*DI
#define SEQ    2048
#define NB     4

#define CLIP5(v) fminf(fmaxf((v), -5.0f), 5.0f)

// scratch (allocation-free rule: __device__ globals)
__device__ float g_xnorm[NTOK * DM];   // LN(x)
__device__ float g_xssm [NTOK * DI];   // x_ssm, later overwritten with y*tanh(gate)
__device__ float g_gate [NTOK * DI];   // tanh(clip(gate))
__device__ float g_out1 [NTOK * DM];   // pre-LN output

// ---------------------------------------------------------------------------
// LayerNorm over last dim (1024). One block per token row, 256 threads,
// 4 elems (one float4) per thread.
// ---------------------------------------------------------------------------
__global__ __launch_bounds__(256) void ln_kernel(
    const float* __restrict__ in, const float* __restrict__ g,
    const float* __restrict__ b, float* __restrict__ out)
{
    __shared__ float s_sum[8], s_sq[8];
    int row = blockIdx.x;
    int tid = threadIdx.x;
    const float4 v = *(const float4*)(in + (size_t)row * DM + tid * 4);

    float sum = v.x + v.y + v.z + v.w;
    float sq  = v.x*v.x + v.y*v.y + v.z*v.z + v.w*v.w;
    // warp reduce
    #pragma unroll
    for (int o = 16; o > 0; o >>= 1) {
        sum += __shfl_xor_sync(0xffffffffu, sum, o);
        sq  += __shfl_xor_sync(0xffffffffu, sq , o);
    }
    int wid = tid >> 5, lid = tid & 31;
    if (lid == 0) { s_sum[wid] = sum; s_sq[wid] = sq; }
    __syncthreads();
    if (wid == 0) {
        float a = (lid < 8) ? s_sum[lid] : 0.f;
        float c = (lid < 8) ? s_sq [lid] : 0.f;
        #pragma unroll
        for (int o = 4; o > 0; o >>= 1) {
            a += __shfl_xor_sync(0xffffffffu, a, o);
            c += __shfl_xor_sync(0xffffffffu, c, o);
        }
        if (lid == 0) { s_sum[0] = a; s_sq[0] = c; }
    }
    __syncthreads();
    float mean = s_sum[0] * (1.0f / DM);
    float var  = s_sq[0] * (1.0f / DM) - mean * mean;
    float rstd = rsqrtf(var + 1e-5f);

    const float4 gv = *(const float4*)(g + tid * 4);
    const float4 bv = *(const float4*)(b + tid * 4);
    float4 o4;
    o4.x = (v.x - mean) * rstd * gv.x + bv.x;
    o4.y = (v.y - mean) * rstd * gv.y + bv.y;
    o4.z = (v.z - mean) * rstd * gv.z + bv.z;
    o4.w = (v.w - mean) * rstd * gv.w + bv.w;
    *(float4*)(out + (size_t)row * DM + tid * 4) = o4;
}

// ---------------------------------------------------------------------------
// Tiled SGEMM: Cmn = sum_k A[m][k] * W[n][k]   (A: MxK rm, W: NxK rm)
// BM=BN=128, BK=16, 256 threads, 8x8 per-thread microtile.
// MODE 0: GEMM1 epilogue -> clip; cols<DI to x_ssm, cols>=DI tanh->gate
// MODE 1: GEMM2 epilogue -> clip -> out0
// M, N, K are multiples of the tile sizes (8192; 3072/1024; 1024/1536).
// ---------------------------------------------------------------------------
template<int MODE>
__global__ __launch_bounds__(256) void gemm_kernel(
    const float* __restrict__ A, const float* __restrict__ W,
    int M, int N, int K,
    float* __restrict__ out0, float* __restrict__ out1)
{
    constexpr int BM = 128, BN = 128, BK = 16;
    __shared__ float As[BK][BM + 4];
    __shared__ float Bs[BK][BN + 4];

    const int bm = blockIdx.y * BM;
    const int bn = blockIdx.x * BN;
    const int tid = threadIdx.x;
    const int tx = tid & 15;        // 0..15 -> n
    const int ty = tid >> 4;        // 0..15 -> m

    float acc[8][8];
    #pragma unroll
    for (int i = 0; i < 8; i++)
        #pragma unroll
        for (int j = 0; j < 8; j++) acc[i][j] = 0.f;

    const int lrow = tid >> 2;          // 0..63
    const int lk   = (tid & 3) * 4;     // 0,4,8,12

    for (int k0 = 0; k0 < K; k0 += BK) {
        #pragma unroll
        for (int r = 0; r < 2; r++) {
            int row = lrow + r * 64;
            float4 v = *(const float4*)&A[(size_t)(bm + row) * K + k0 + lk];
            As[lk + 0][row] = v.x; As[lk + 1][row] = v.y;
            As[lk + 2][row] = v.z; As[lk + 3][row] = v.w;
        }
        #pragma unroll
        for (int r = 0; r < 2; r++) {
            int row = lrow + r * 64;
            float4 v = *(const float4*)&W[(size_t)(bn + row) * K + k0 + lk];
            Bs[lk + 0][row] = v.x; Bs[lk + 1][row] = v.y;
            Bs[lk + 2][row] = v.z; Bs[lk + 3][row] = v.w;
        }
        __syncthreads();

        #pragma unroll
        for (int k = 0; k < BK; k++) {
            float a[8], bv[8];
            *(float4*)&a[0]  = *(const float4*)&As[k][ty * 8];
            *(float4*)&a[4]  = *(const float4*)&As[k][ty * 8 + 4];
            *(float4*)&bv[0] = *(const float4*)&Bs[k][tx * 8];
            *(float4*)&bv[4] = *(const float4*)&Bs[k][tx * 8 + 4];
            #pragma unroll
            for (int i = 0; i < 8; i++)
                #pragma unroll
                for (int j = 0; j < 8; j++)
                    acc[i][j] = fmaf(a[i], bv[j], acc[i][j]);
        }
        __syncthreads();
    }

    #pragma unroll
    for (int i = 0; i < 8; i++) {
        int row = bm + ty * 8 + i;
        #pragma unroll
        for (int j = 0; j < 8; j++) {
            int col = bn + tx * 8 + j;
            float v = CLIP5(acc[i][j]);
            if (MODE == 0) {
                if (col < DI) out0[(size_t)row * DI + col] = v;
                else          out1[(size_t)row * DI + (col - DI)] = tanhf(v);
            } else {
                out0[(size_t)row * DM + col] = v;
            }
        }
    }
}

// ---------------------------------------------------------------------------
// Sequential SSM scan. One thread per (batch, inner-channel): 6144 threads.
// h (8 states) lives in registers; x_ssm read / y*tanh(gate) written in place.
// Consecutive threads handle consecutive i -> coalesced per-timestep access.
// ---------------------------------------------------------------------------
__global__ __launch_bounds__(128) void scan_kernel(
    const float* __restrict__ A_log, const float* __restrict__ Bm,
    const float* __restrict__ Cm)
{
    int idx = blockIdx.x * blockDim.x + threadIdx.x;   // 0..6143
    int b = idx / DI;
    int i = idx - b * DI;

    float decay[DS], bs[DS], cs[DS], h[DS];
    #pragma unroll
    for (int s = 0; s < DS; s++) {
        float a = A_log[i * DS + s];
        a = fminf(fmaxf(a, -5.0f), 0.0f);
        float Av = -__expf(a);
        Av = fminf(fmaxf(Av, -2.0f), -0.01f);
        decay[s] = Av * 0.9f;
        bs[s] = Bm[i * DS + s] * 0.1f;
        cs[s] = Cm[i * DS + s];
        h[s] = 0.f;
    }

    const float* __restrict__ xin = g_xssm + (size_t)b * SEQ * DI + i;
    const float* __restrict__ gin = g_gate + (size_t)b * SEQ * DI + i;
    float* __restrict__ yout = g_xssm + (size_t)b * SEQ * DI + i;

    #pragma unroll 4
    for (int t = 0; t < SEQ; t++) {
        float x = xin[(size_t)t * DI];
        float gt = gin[(size_t)t * DI];
        float y = 0.f;
        #pragma unroll
        for (int s = 0; s < DS; s++) {
            float hs = fmaf(h[s], decay[s], x * bs[s]);
            hs = CLIP5(hs);
            h[s] = hs;
            y = fmaf(hs, cs[s], y);
        }
        y = CLIP5(y);
        yout[(size_t)t * DI] = y * gt;
    }
}

// Note: __expf vs expf — A_log clipped to [-5,0], exp in [0.0067,1], then
// result further clipped to [-2,-0.01]; __expf max rel err ~2^-21 here, fine.

// ---------------------------------------------------------------------------
extern "C" void kernel_launch(void* const* d_in, const int* in_sizes, int n_in,
                              void* d_out, int out_size)
{
    const float* x       = (const float*)d_in[0];
    const float* W_in    = (const float*)d_in[1];
    const float* W_out   = (const float*)d_in[2];
    const float* A_log   = (const float*)d_in[3];
    const float* Bm      = (const float*)d_in[4];
    const float* Cm      = (const float*)d_in[5];
    const float* ln_in_g = (const float*)d_in[6];
    const float* ln_in_b = (const float*)d_in[7];
    const float* ln_out_g= (const float*)d_in[8];
    const float* ln_out_b= (const float*)d_in[9];
    float* out = (float*)d_out;

    float *p_xnorm, *p_xssm, *p_gate, *p_out1;
    cudaGetSymbolAddress((void**)&p_xnorm, g_xnorm);
    cudaGetSymbolAddress((void**)&p_xssm , g_xssm);
    cudaGetSymbolAddress((void**)&p_gate , g_gate);
    cudaGetSymbolAddress((void**)&p_out1 , g_out1);

    // 1) input LayerNorm
    ln_kernel<<<NTOK, 256>>>(x, ln_in_g, ln_in_b, p_xnorm);

    // 2) GEMM1: [8192 x 3072] = xnorm @ W_in^T ; clip, split, tanh(gate)
    {
        dim3 grid(NDI2 / 128, NTOK / 128);
        gemm_kernel<0><<<grid, 256>>>(p_xnorm, W_in, NTOK, NDI2, DM,
                                      p_xssm, p_gate);
    }

    // 3) sequential scan (writes y*tanh(gate) in place over x_ssm)
    scan_kernel<<<(NB * DI) / 128, 128>>>(A_log, Bm, Cm);

    // 4) GEMM2: [8192 x 1024] = (y*gate) @ W_out^T ; clip
    {
        dim3 grid(DM / 128, NTOK / 128);
        gemm_kernel<1><<<grid, 256>>>(p_xssm, W_out, NTOK, DM, DI,
                                      p_out1, nullptr);
    }

    // 5) output LayerNorm -> d_out
    ln_kernel<<<NTOK, 256>>>(p_out1, ln_out_g, ln_out_b, out);
}

// round 5
// speedup vs baseline: 1.6066x; 1.6066x over previous
#include <cuda_runtime.h>
#include <cstdint>

// ---------------------------------------------------------------------------
// SimplifiedMamba2Block on GB300 (sm_103a), compute_103-safe tensor path:
//   LN(round tf32) -> mma.sync tf32 GEMM1 (+clip/split/tanh) -> SSM scan
//   (rounds output) -> mma.sync tf32 GEMM2 (+clip) -> LN
// tcgen05 is rejected by ptxas at target 'sm_103' (no -a suffix in harness
// lowering), so we use the portable sm_80+ mma.sync tf32 instructions.
// ---------------------------------------------------------------------------

#define NTOK   8192
#define DM     1024
#define DI     1536
#define DS     8
#define NDI2   3072
#define SEQ    2048
#define NB     4

#define CLIP5(v) fminf(fmaxf((v), -5.0f), 5.0f)

// scratch (__device__ globals per allocation-free rule)
__device__ float g_xnorm[NTOK * DM];    // LN(x), tf32-rounded
__device__ float g_xssm [NTOK * DI];    // GEMM1 out (ssm half), fp32
__device__ float g_gate [NTOK * DI];    // tanh gate -> scan writes tf32(y*gate)
__device__ float g_out1 [NTOK * DM];    // GEMM2 out, fp32
__device__ float g_win  [NDI2 * DM];    // tf32-rounded W_in
__device__ float g_wout [DM * DI];      // tf32-rounded W_out

// ======================= helpers ===========================================
__device__ __forceinline__ uint32_t smem_u32(const void* p) {
    uint32_t r;
    asm("{ .reg .u64 t; cvta.to.shared.u64 t, %1; cvt.u32.u64 %0, t; }"
        : "=r"(r) : "l"(p));
    return r;
}
__device__ __forceinline__ float to_tf32(float x) {   // round-to-nearest tf32
    float r; asm("cvt.rna.tf32.f32 %0, %1;" : "=f"(r) : "f"(x)); return r;
}
__device__ __forceinline__ void cp_async16(uint32_t saddr, const void* gaddr) {
    asm volatile("cp.async.cg.shared.global [%0], [%1], 16;"
                 :: "r"(saddr), "l"(gaddr) : "memory");
}
#define CP_COMMIT() asm volatile("cp.async.commit_group;" ::: "memory")
#define CP_WAIT(n)  asm volatile("cp.async.wait_group %0;" :: "n"(n) : "memory")

// m16n8k8 tf32 MMA (row.col), D += A*B
__device__ __forceinline__ void mma_tf32(float* d, const float* a, const float* b) {
    asm volatile(
        "mma.sync.aligned.m16n8k8.row.col.f32.tf32.tf32.f32 "
        "{%0,%1,%2,%3}, {%4,%5,%6,%7}, {%8,%9}, {%0,%1,%2,%3};"
        : "+f"(d[0]), "+f"(d[1]), "+f"(d[2]), "+f"(d[3])
        : "r"(__float_as_uint(a[0])), "r"(__float_as_uint(a[1])),
          "r"(__float_as_uint(a[2])), "r"(__float_as_uint(a[3])),
          "r"(__float_as_uint(b[0])), "r"(__float_as_uint(b[1])));
}

// ======================= weight prep (tf32 round) ===========================
__global__ __launch_bounds__(256) void prep_w(
    const float* __restrict__ win, const float* __restrict__ wout)
{
    const int n1 = (NDI2 * DM) / 4;
    const int n2 = (DM * DI) / 4;
    int i = blockIdx.x * blockDim.x + threadIdx.x;
    if (i < n1) {
        float4 v = ((const float4*)win)[i];
        v.x = to_tf32(v.x); v.y = to_tf32(v.y);
        v.z = to_tf32(v.z); v.w = to_tf32(v.w);
        ((float4*)g_win)[i] = v;
    } else if (i < n1 + n2) {
        float4 v = ((const float4*)wout)[i - n1];
        v.x = to_tf32(v.x); v.y = to_tf32(v.y);
        v.z = to_tf32(v.z); v.w = to_tf32(v.w);
        ((float4*)g_wout)[i - n1] = v;
    }
}

// ======================= LayerNorm =========================================
template<bool ROUND>
__global__ __launch_bounds__(256) void ln_kernel(
    const float* __restrict__ in, const float* __restrict__ g,
    const float* __restrict__ b, float* __restrict__ out)
{
    __shared__ float s_sum[8], s_sq[8];
    int row = blockIdx.x;
    int tid = threadIdx.x;
    const float4 v = *(const float4*)(in + (size_t)row * DM + tid * 4);

    float sum = v.x + v.y + v.z + v.w;
    float sq  = v.x*v.x + v.y*v.y + v.z*v.z + v.w*v.w;
    #pragma unroll
    for (int o = 16; o > 0; o >>= 1) {
        sum += __shfl_xor_sync(0xffffffffu, sum, o);
        sq  += __shfl_xor_sync(0xffffffffu, sq , o);
    }
    int wid = tid >> 5, lid = tid & 31;
    if (lid == 0) { s_sum[wid] = sum; s_sq[wid] = sq; }
    __syncthreads();
    if (wid == 0) {
        float a = (lid < 8) ? s_sum[lid] : 0.f;
        float c = (lid < 8) ? s_sq [lid] : 0.f;
        #pragma unroll
        for (int o = 4; o > 0; o >>= 1) {
            a += __shfl_xor_sync(0xffffffffu, a, o);
            c += __shfl_xor_sync(0xffffffffu, c, o);
        }
        if (lid == 0) { s_sum[0] = a; s_sq[0] = c; }
    }
    __syncthreads();
    float mean = s_sum[0] * (1.0f / DM);
    float var  = s_sq[0] * (1.0f / DM) - mean * mean;
    float rstd = rsqrtf(var + 1e-5f);

    const float4 gv = *(const float4*)(g + tid * 4);
    const float4 bv = *(const float4*)(b + tid * 4);
    float4 o4;
    o4.x = (v.x - mean) * rstd * gv.x + bv.x;
    o4.y = (v.y - mean) * rstd * gv.y + bv.y;
    o4.z = (v.z - mean) * rstd * gv.z + bv.z;
    o4.w = (v.w - mean) * rstd * gv.w + bv.w;
    if (ROUND) {
        o4.x = to_tf32(o4.x); o4.y = to_tf32(o4.y);
        o4.z = to_tf32(o4.z); o4.w = to_tf32(o4.w);
    }
    *(float4*)(out + (size_t)row * DM + tid * 4) = o4;
}

// ======================= mma.sync tf32 GEMM =================================
// C[128,128] per CTA. C = A @ W^T, A: MxK rm, W: NxK rm. K % 16 == 0.
// 256 threads = 8 warps in a 4(m) x 2(n) grid; warp tile 32x64;
// per warp per BK=16: 2 m-tiles x 8 n-tiles x 2 k-steps of m16n8k8.
// Smem double-buffered, cp.async.cg, row stride 20 floats (conflict-free).
// MODE 0: clip; cols<DI -> out0 (x_ssm), cols>=DI -> tanh -> out1 (gate)
// MODE 1: clip -> out0
// ---------------------------------------------------------------------------
#define BK     16
#define LDS_ST 20     // row stride in floats (BK + 4 pad)

template<int MODE>
__global__ __launch_bounds__(256, 2) void mma_gemm(
    const float* __restrict__ A, const float* __restrict__ W,
    int K, float* __restrict__ out0, float* __restrict__ out1)
{
    __shared__ float As[2][128 * LDS_ST];
    __shared__ float Ws[2][128 * LDS_ST];

    const int tid  = threadIdx.x;
    const int lane = tid & 31;
    const int wid  = tid >> 5;
    const int wm   = wid & 3;          // warp m index (0..3)
    const int wn   = wid >> 2;         // warp n index (0..1)
    const int bm   = blockIdx.y * 128;
    const int bn   = blockIdx.x * 128;

    float acc[2][8][4];
    #pragma unroll
    for (int mt = 0; mt < 2; mt++)
        #pragma unroll
        for (int nt = 0; nt < 8; nt++)
            #pragma unroll
            for (int f = 0; f < 4; f++) acc[mt][nt][f] = 0.f;

    // cp.async addressing: each thread copies 2 rows x 1 float4 per tile
    const int lr = tid >> 2;           // 0..63
    const int lq = tid & 3;            // quarter of a 16-float row
    const float* gA = A + (size_t)(bm + lr) * K + lq * 4;
    const float* gW = W + (size_t)(bn + lr) * K + lq * 4;
    const uint32_t sA0 = smem_u32(&As[0][0]);
    const uint32_t sW0 = smem_u32(&Ws[0][0]);
    const uint32_t bufBytes = 128 * LDS_ST * 4;

    const int NC = K / BK;

    // prologue: tile 0
    {
        #pragma unroll
        for (int r = 0; r < 2; r++) {
            uint32_t doff = ((lr + r * 64) * LDS_ST + lq * 4) * 4;
            cp_async16(sA0 + doff, gA + (size_t)(r * 64) * K);
            cp_async16(sW0 + doff, gW + (size_t)(r * 64) * K);
        }
        CP_COMMIT();
    }

    const int ar = lane >> 2;          // fragment row-in-8
    const int ac = lane & 3;           // fragment k-in-4

    for (int c = 0; c < NC; c++) {
        const int buf = c & 1;
        if (c + 1 < NC) {
            const int nb = buf ^ 1;
            #pragma unroll
            for (int r = 0; r < 2; r++) {
                uint32_t doff = nb * bufBytes + ((lr + r * 64) * LDS_ST + lq * 4) * 4;
                cp_async16(sA0 + doff, gA + (size_t)(r * 64) * K + (c + 1) * BK);
                cp_async16(sW0 + doff, gW + (size_t)(r * 64) * K + (c + 1) * BK);
            }
            CP_COMMIT();
            CP_WAIT(1);                // tile c resident
        } else {
            CP_WAIT(0);
        }
        __syncthreads();

        #pragma unroll
        for (int ks = 0; ks < 2; ks++) {
            const int k0 = ks * 8;
            float a[2][4], b[8][2];
            #pragma unroll
            for (int mt = 0; mt < 2; mt++) {
                const float* p = &As[buf][(wm * 32 + mt * 16 + ar) * LDS_ST + k0 + ac];
                a[mt][0] = p[0];
                a[mt][1] = p[8 * LDS_ST];
                a[mt][2] = p[4];
                a[mt][3] = p[8 * LDS_ST + 4];
            }
            #pragma unroll
            for (int nt = 0; nt < 8; nt++) {
                const float* p = &Ws[buf][(wn * 64 + nt * 8 + ar) * LDS_ST + k0 + ac];
                b[nt][0] = p[0];
                b[nt][1] = p[4];
            }
            #pragma unroll
            for (int mt = 0; mt < 2; mt++)
                #pragma unroll
                for (int nt = 0; nt < 8; nt++)
                    mma_tf32(acc[mt][nt], a[mt], b[nt]);
        }
        __syncthreads();
    }

    // epilogue
    #pragma unroll
    for (int mt = 0; mt < 2; mt++) {
        #pragma unroll
        for (int nt = 0; nt < 8; nt++) {
            const int row0 = bm + wm * 32 + mt * 16 + (lane >> 2);
            const int col  = bn + wn * 64 + nt * 8 + (lane & 3) * 2;
            #pragma unroll
            for (int hh = 0; hh < 2; hh++) {
                const int row = row0 + hh * 8;
                float v0 = CLIP5(acc[mt][nt][hh * 2 + 0]);
                float v1 = CLIP5(acc[mt][nt][hh * 2 + 1]);
                if (MODE == 0) {
                    if (col < DI) {
                        float2 o = make_float2(v0, v1);
                        *(float2*)(out0 + (size_t)row * DI + col) = o;
                    } else {
                        float2 o = make_float2(tanhf(v0), tanhf(v1));
                        *(float2*)(out1 + (size_t)row * DI + (col - DI)) = o;
                    }
                } else {
                    float2 o = make_float2(v0, v1);
                    *(float2*)(out0 + (size_t)row * DM + col) = o;
                }
            }
        }
    }
}

// ======================= SSM scan ===========================================
// One thread per (batch, channel). Reads g_xssm + g_gate (restrict, read-only
// streams), writes tf32(y*gate) into g_gate -> no aliasing on the x stream.
// ---------------------------------------------------------------------------
__global__ __launch_bounds__(128) void scan_kernel(
    const float* __restrict__ A_log, const float* __restrict__ Bm,
    const float* __restrict__ Cm)
{
    int idx = blockIdx.x * blockDim.x + threadIdx.x;   // 0..6143
    int b = idx / DI;
    int i = idx - b * DI;

    float decay[DS], bs[DS], cs[DS], hreg[DS];
    #pragma unroll
    for (int s = 0; s < DS; s++) {
        float a = A_log[i * DS + s];
        a = fminf(fmaxf(a, -5.0f), 0.0f);
        float Av = -__expf(a);
        Av = fminf(fmaxf(Av, -2.0f), -0.01f);
        decay[s] = Av * 0.9f;
        bs[s] = Bm[i * DS + s] * 0.1f;
        cs[s] = Cm[i * DS + s];
        hreg[s] = 0.f;
    }

    const float* __restrict__ xin  = g_xssm + (size_t)b * SEQ * DI + i;
    const float* __restrict__ gin  = g_gate + (size_t)b * SEQ * DI + i;
    float*       __restrict__ yout = g_gate + (size_t)b * SEQ * DI + i;

    #pragma unroll 8
    for (int t = 0; t < SEQ; t++) {
        float x  = xin[(size_t)t * DI];
        float gt = gin[(size_t)t * DI];
        float y = 0.f;
        #pragma unroll
        for (int s = 0; s < DS; s++) {
            float hs = fmaf(hreg[s], decay[s], x * bs[s]);
            hs = CLIP5(hs);
            hreg[s] = hs;
            y = fmaf(hs, cs[s], y);
        }
        y = CLIP5(y);
        yout[(size_t)t * DI] = to_tf32(y * gt);   // tf32 for GEMM2 A-operand
    }
}

// ======================= launch =============================================
extern "C" void kernel_launch(void* const* d_in, const int* in_sizes, int n_in,
                              void* d_out, int out_size)
{
    const float* x       = (const float*)d_in[0];
    const float* W_in    = (const float*)d_in[1];
    const float* W_out   = (const float*)d_in[2];
    const float* A_log   = (const float*)d_in[3];
    const float* Bm      = (const float*)d_in[4];
    const float* Cm      = (const float*)d_in[5];
    const float* ln_in_g = (const float*)d_in[6];
    const float* ln_in_b = (const float*)d_in[7];
    const float* ln_out_g= (const float*)d_in[8];
    const float* ln_out_b= (const float*)d_in[9];
    float* out = (float*)d_out;

    float *p_xnorm, *p_xssm, *p_gate, *p_out1, *p_win, *p_wout;
    cudaGetSymbolAddress((void**)&p_xnorm, g_xnorm);
    cudaGetSymbolAddress((void**)&p_xssm , g_xssm);
    cudaGetSymbolAddress((void**)&p_gate , g_gate);
    cudaGetSymbolAddress((void**)&p_out1 , g_out1);
    cudaGetSymbolAddress((void**)&p_win  , g_win);
    cudaGetSymbolAddress((void**)&p_wout , g_wout);

    // 0) round weights to tf32 scratch copies
    {
        int total4 = (NDI2 * DM + DM * DI) / 4;
        prep_w<<<(total4 + 255) / 256, 256>>>(W_in, W_out);
    }

    // 1) input LN (tf32-rounded output)
    ln_kernel<true><<<NTOK, 256>>>(x, ln_in_g, ln_in_b, p_xnorm);

    // 2) GEMM1: [8192 x 3072] = LN(x) @ W_in^T, clip/split/tanh
    {
        dim3 grid(NDI2 / 128, NTOK / 128);
        mma_gemm<0><<<grid, 256>>>(p_xnorm, p_win, DM, p_xssm, p_gate);
    }

    // 3) scan: tf32(y*tanh(gate)) -> g_gate
    scan_kernel<<<(NB * DI) / 128, 128>>>(A_log, Bm, Cm);

    // 4) GEMM2: [8192 x 1024] = (y*gate) @ W_out^T, clip
    {
        dim3 grid(DM / 128, NTOK / 128);
        mma_gemm<1><<<grid, 256>>>(p_gate, p_wout, DI, p_out1, nullptr);
    }

    // 5) output LN (no rounding)
    ln_kernel<false><<<NTOK, 256>>>(p_out1, ln_out_g, ln_out_b, out);
}

// round 6
// speedup vs baseline: 1.9442x; 1.2101x over previous
#include <cuda_runtime.h>
#include <cuda_fp16.h>
#include <cstdint>

// ---------------------------------------------------------------------------
// SimplifiedMamba2Block on GB300 (sm_103a), compute_103-safe tensor path:
//   LN(->fp16) -> mma.sync f16 m16n8k16 GEMM1 (+clip/split/tanh) -> SSM scan
//   (->fp16) -> mma.sync f16 GEMM2 (+clip) -> LN
// fp16 mantissa (11 bit) == tf32 mantissa, but m16n8k16 does 2x MAC/instr on
// the de-rated legacy tensor pipe -> half the GEMM instruction count.
// ---------------------------------------------------------------------------

#define NTOK   8192
#define DM     1024
#define DI     1536
#define DS     8
#define NDI2   3072
#define SEQ    2048
#define NB     4

#define CLIP5(v) fminf(fmaxf((v), -5.0f), 5.0f)

// scratch (__device__ globals per allocation-free rule)
__device__ __half g_xnorm[NTOK * DM];    // LN(x) in fp16
__device__ float  g_xssm [NTOK * DI];    // GEMM1 out (ssm half), fp32
__device__ float  g_gate [NTOK * DI];    // tanh gate, fp32
__device__ __half g_y    [NTOK * DI];    // scan out y*gate, fp16 (GEMM2 A)
__device__ float  g_out1 [NTOK * DM];    // GEMM2 out, fp32
__device__ __half g_win  [NDI2 * DM];    // fp16 W_in
__device__ __half g_wout [DM * DI];      // fp16 W_out

// ======================= helpers ===========================================
__device__ __forceinline__ uint32_t smem_u32(const void* p) {
    uint32_t r;
    asm("{ .reg .u64 t; cvta.to.shared.u64 t, %1; cvt.u32.u64 %0, t; }"
        : "=r"(r) : "l"(p));
    return r;
}
__device__ __forceinline__ void cp_async16(uint32_t saddr, const void* gaddr) {
    asm volatile("cp.async.cg.shared.global [%0], [%1], 16;"
                 :: "r"(saddr), "l"(gaddr) : "memory");
}
#define CP_COMMIT() asm volatile("cp.async.commit_group;" ::: "memory")
#define CP_WAIT(n)  asm volatile("cp.async.wait_group %0;" :: "n"(n) : "memory")

// m16n8k16 f16 MMA (row.col), fp32 accumulate: D += A*B
__device__ __forceinline__ void mma_f16(float* d, const uint32_t* a, const uint32_t* b) {
    asm volatile(
        "mma.sync.aligned.m16n8k16.row.col.f32.f16.f16.f32 "
        "{%0,%1,%2,%3}, {%4,%5,%6,%7}, {%8,%9}, {%0,%1,%2,%3};"
        : "+f"(d[0]), "+f"(d[1]), "+f"(d[2]), "+f"(d[3])
        : "r"(a[0]), "r"(a[1]), "r"(a[2]), "r"(a[3]), "r"(b[0]), "r"(b[1]));
}

// ======================= weight prep (fp32 -> fp16) =========================
__global__ __launch_bounds__(256) void prep_w(
    const float* __restrict__ win, const float* __restrict__ wout)
{
    const int n1 = (NDI2 * DM) / 4;
    const int n2 = (DM * DI) / 4;
    int i = blockIdx.x * blockDim.x + threadIdx.x;
    if (i < n1) {
        float4 v = ((const float4*)win)[i];
        __half2 h0 = __floats2half2_rn(v.x, v.y);
        __half2 h1 = __floats2half2_rn(v.z, v.w);
        uint2 u; u.x = *(uint32_t*)&h0; u.y = *(uint32_t*)&h1;
        ((uint2*)g_win)[i] = u;
    } else if (i < n1 + n2) {
        float4 v = ((const float4*)wout)[i - n1];
        __half2 h0 = __floats2half2_rn(v.x, v.y);
        __half2 h1 = __floats2half2_rn(v.z, v.w);
        uint2 u; u.x = *(uint32_t*)&h0; u.y = *(uint32_t*)&h1;
        ((uint2*)g_wout)[i - n1] = u;
    }
}

// ======================= LayerNorm =========================================
// HALF_OUT=1 -> write fp16 (GEMM operand); HALF_OUT=0 -> write fp32 (final).
template<int HALF_OUT>
__global__ __launch_bounds__(256) void ln_kernel(
    const float* __restrict__ in, const float* __restrict__ g,
    const float* __restrict__ b, void* __restrict__ outv)
{
    __shared__ float s_sum[8], s_sq[8];
    int row = blockIdx.x;
    int tid = threadIdx.x;
    const float4 v = *(const float4*)(in + (size_t)row * DM + tid * 4);

    float sum = v.x + v.y + v.z + v.w;
    float sq  = v.x*v.x + v.y*v.y + v.z*v.z + v.w*v.w;
    #pragma unroll
    for (int o = 16; o > 0; o >>= 1) {
        sum += __shfl_xor_sync(0xffffffffu, sum, o);
        sq  += __shfl_xor_sync(0xffffffffu, sq , o);
    }
    int wid = tid >> 5, lid = tid & 31;
    if (lid == 0) { s_sum[wid] = sum; s_sq[wid] = sq; }
    __syncthreads();
    if (wid == 0) {
        float a = (lid < 8) ? s_sum[lid] : 0.f;
        float c = (lid < 8) ? s_sq [lid] : 0.f;
        #pragma unroll
        for (int o = 4; o > 0; o >>= 1) {
            a += __shfl_xor_sync(0xffffffffu, a, o);
            c += __shfl_xor_sync(0xffffffffu, c, o);
        }
        if (lid == 0) { s_sum[0] = a; s_sq[0] = c; }
    }
    __syncthreads();
    float mean = s_sum[0] * (1.0f / DM);
    float var  = s_sq[0] * (1.0f / DM) - mean * mean;
    float rstd = rsqrtf(var + 1e-5f);

    const float4 gv = *(const float4*)(g + tid * 4);
    const float4 bv = *(const float4*)(b + tid * 4);
    float4 o4;
    o4.x = (v.x - mean) * rstd * gv.x + bv.x;
    o4.y = (v.y - mean) * rstd * gv.y + bv.y;
    o4.z = (v.z - mean) * rstd * gv.z + bv.z;
    o4.w = (v.w - mean) * rstd * gv.w + bv.w;
    if (HALF_OUT) {
        __half2 h0 = __floats2half2_rn(o4.x, o4.y);
        __half2 h1 = __floats2half2_rn(o4.z, o4.w);
        uint2 u; u.x = *(uint32_t*)&h0; u.y = *(uint32_t*)&h1;
        *(uint2*)((__half*)outv + (size_t)row * DM + tid * 4) = u;
    } else {
        *(float4*)((float*)outv + (size_t)row * DM + tid * 4) = o4;
    }
}

// ======================= mma.sync f16 GEMM ==================================
// C[128,128] per CTA. C = A @ W^T, A: MxK rm fp16, W: NxK rm fp16. K%32==0.
// 256 threads = 8 warps, 4(m) x 2(n); warp tile 32x64.
// BK=32 halves/tile; 3-stage cp.async ring; ONE __syncthreads per tile.
// smem row stride 40 halves (80B) -> LDS conflict-free; 20480B/stage.
// MODE 0: clip; cols<DI -> out0 (x_ssm), else tanh -> out1 (gate)  [fp32]
// MODE 1: clip -> out0 [fp32]
// ---------------------------------------------------------------------------
#define ST      40           // smem row stride in halves
#define STAGEB  20480u       // bytes per stage (A 10240 + W 10240)
#define GEMM_SMEM (3 * STAGEB)

template<int MODE>
__global__ __launch_bounds__(256, 2) void mma_gemm(
    const __half* __restrict__ A, const __half* __restrict__ W,
    int K, float* __restrict__ out0, float* __restrict__ out1)
{
    extern __shared__ __align__(16) char dynsmem[];

    const int tid  = threadIdx.x;
    const int lane = tid & 31;
    const int wid  = tid >> 5;
    const int wm   = wid & 3;          // warp m index (0..3)
    const int wn   = wid >> 2;         // warp n index (0..1)
    const int bm   = blockIdx.y * 128;
    const int bn   = blockIdx.x * 128;

    float acc[2][8][4];
    #pragma unroll
    for (int mt = 0; mt < 2; mt++)
        #pragma unroll
        for (int nt = 0; nt < 8; nt++)
            #pragma unroll
            for (int f = 0; f < 4; f++) acc[mt][nt][f] = 0.f;

    // fill addressing: thread -> rows lr, lr+64 of both A and W, 16B seg lq
    const int lr = tid >> 2;           // 0..63
    const int lq = tid & 3;            // 16-byte segment (8 halves)
    const __half* gA = A + (size_t)(bm + lr) * K + lq * 8;
    const __half* gW = W + (size_t)(bn + lr) * K + lq * 8;
    const uint32_t sbase = smem_u32(dynsmem);
    const uint32_t fo1 = (uint32_t)lr * 80u + (uint32_t)lq * 16u;
    const uint32_t fo2 = (uint32_t)(lr + 64) * 80u + (uint32_t)lq * 16u;

    const int NC = K / 32;

    // prologue: tiles 0,1 into stages 0,1
    #pragma unroll
    for (int t = 0; t < 2; t++) {
        uint32_t base = sbase + t * STAGEB;
        const __half* at = gA + t * 32;
        const __half* wt = gW + t * 32;
        cp_async16(base + fo1,           at);
        cp_async16(base + fo2,           at + (size_t)64 * K);
        cp_async16(base + 10240u + fo1,  wt);
        cp_async16(base + 10240u + fo2,  wt + (size_t)64 * K);
        CP_COMMIT();
    }

    const int ar = lane >> 2;          // fragment row-in-8
    const int ac = lane & 3;           // fragment k-pair index

    for (int c = 0; c < NC; c++) {
        const int st = c % 3;
        if (c + 1 < NC) { CP_WAIT(1); } else { CP_WAIT(0); }
        __syncthreads();               // tile c visible; stage (c+2)%3 free

        if (c + 2 < NC) {              // prefetch tile c+2 (overlaps compute)
            uint32_t base = sbase + ((c + 2) % 3) * STAGEB;
            const __half* at = gA + (c + 2) * 32;
            const __half* wt = gW + (c + 2) * 32;
            cp_async16(base + fo1,           at);
            cp_async16(base + fo2,           at + (size_t)64 * K);
            cp_async16(base + 10240u + fo1,  wt);
            cp_async16(base + 10240u + fo2,  wt + (size_t)64 * K);
            CP_COMMIT();
        }

        const __half* sAh = (const __half*)(dynsmem + st * STAGEB);
        const __half* sWh = (const __half*)(dynsmem + st * STAGEB + 10240u);

        #pragma unroll
        for (int ks = 0; ks < 2; ks++) {
            const int k0 = ks * 16;
            uint32_t a[2][4], b[8][2];
            #pragma unroll
            for (int mt = 0; mt < 2; mt++) {
                const __half* p = sAh + (wm * 32 + mt * 16 + ar) * ST + k0 + ac * 2;
                a[mt][0] = *(const uint32_t*)(p);
                a[mt][1] = *(const uint32_t*)(p + 8 * ST);
                a[mt][2] = *(const uint32_t*)(p + 8);
                a[mt][3] = *(const uint32_t*)(p + 8 * ST + 8);
            }
            #pragma unroll
            for (int nt = 0; nt < 8; nt++) {
                const __half* p = sWh + (wn * 64 + nt * 8 + ar) * ST + k0 + ac * 2;
                b[nt][0] = *(const uint32_t*)(p);
                b[nt][1] = *(const uint32_t*)(p + 8);
            }
            #pragma unroll
            for (int mt = 0; mt < 2; mt++)
                #pragma unroll
                for (int nt = 0; nt < 8; nt++)
                    mma_f16(acc[mt][nt], a[mt], b[nt]);
        }
    }

    // epilogue (D layout: c0,c1 @ row=lane/4, col=2*(lane%4); c2,c3 @ row+8)
    #pragma unroll
    for (int mt = 0; mt < 2; mt++) {
        #pragma unroll
        for (int nt = 0; nt < 8; nt++) {
            const int row0 = bm + wm * 32 + mt * 16 + (lane >> 2);
            const int col  = bn + wn * 64 + nt * 8 + (lane & 3) * 2;
            #pragma unroll
            for (int hh = 0; hh < 2; hh++) {
                const int row = row0 + hh * 8;
                float v0 = CLIP5(acc[mt][nt][hh * 2 + 0]);
                float v1 = CLIP5(acc[mt][nt][hh * 2 + 1]);
                if (MODE == 0) {
                    if (col < DI) {
                        *(float2*)(out0 + (size_t)row * DI + col) = make_float2(v0, v1);
                    } else {
                        *(float2*)(out1 + (size_t)row * DI + (col - DI)) =
                            make_float2(tanhf(v0), tanhf(v1));
                    }
                } else {
                    *(float2*)(out0 + (size_t)row * DM + col) = make_float2(v0, v1);
                }
            }
        }
    }
}

// ======================= SSM scan ===========================================
// One thread per (batch, channel); h in regs; reads fp32 x_ssm/gate streams,
// writes fp16 y*gate (GEMM2 A operand) to a separate buffer (no aliasing).
// ---------------------------------------------------------------------------
__global__ __launch_bounds__(128) void scan_kernel(
    const float* __restrict__ A_log, const float* __restrict__ Bm,
    const float* __restrict__ Cm)
{
    int idx = blockIdx.x * blockDim.x + threadIdx.x;   // 0..6143
    int b = idx / DI;
    int i = idx - b * DI;

    float decay[DS], bs[DS], cs[DS], hreg[DS];
    #pragma unroll
    for (int s = 0; s < DS; s++) {
        float a = A_log[i * DS + s];
        a = fminf(fmaxf(a, -5.0f), 0.0f);
        float Av = -__expf(a);
        Av = fminf(fmaxf(Av, -2.0f), -0.01f);
        decay[s] = Av * 0.9f;
        bs[s] = Bm[i * DS + s] * 0.1f;
        cs[s] = Cm[i * DS + s];
        hreg[s] = 0.f;
    }

    const float* __restrict__ xin  = g_xssm + (size_t)b * SEQ * DI + i;
    const float* __restrict__ gin  = g_gate + (size_t)b * SEQ * DI + i;
    __half*      __restrict__ yout = g_y    + (size_t)b * SEQ * DI + i;

    #pragma unroll 8
    for (int t = 0; t < SEQ; t++) {
        float x  = xin[(size_t)t * DI];
        float gt = gin[(size_t)t * DI];
        float y = 0.f;
        #pragma unroll
        for (int s = 0; s < DS; s++) {
            float hs = fmaf(hreg[s], decay[s], x * bs[s]);
            hs = CLIP5(hs);
            hreg[s] = hs;
            y = fmaf(hs, cs[s], y);
        }
        y = CLIP5(y);
        yout[(size_t)t * DI] = __float2half_rn(y * gt);
    }
}

// ======================= launch =============================================
extern "C" void kernel_launch(void* const* d_in, const int* in_sizes, int n_in,
                              void* d_out, int out_size)
{
    const float* x       = (const float*)d_in[0];
    const float* W_in    = (const float*)d_in[1];
    const float* W_out   = (const float*)d_in[2];
    const float* A_log   = (const float*)d_in[3];
    const float* Bm      = (const float*)d_in[4];
    const float* Cm      = (const float*)d_in[5];
    const float* ln_in_g = (const float*)d_in[6];
    const float* ln_in_b = (const float*)d_in[7];
    const float* ln_out_g= (const float*)d_in[8];
    const float* ln_out_b= (const float*)d_in[9];
    float* out = (float*)d_out;

    __half *p_xnorm, *p_y, *p_win, *p_wout;
    float *p_xssm, *p_gate, *p_out1;
    cudaGetSymbolAddress((void**)&p_xnorm, g_xnorm);
    cudaGetSymbolAddress((void**)&p_xssm , g_xssm);
    cudaGetSymbolAddress((void**)&p_gate , g_gate);
    cudaGetSymbolAddress((void**)&p_y    , g_y);
    cudaGetSymbolAddress((void**)&p_out1 , g_out1);
    cudaGetSymbolAddress((void**)&p_win  , g_win);
    cudaGetSymbolAddress((void**)&p_wout , g_wout);

    cudaFuncSetAttribute(mma_gemm<0>, cudaFuncAttributeMaxDynamicSharedMemorySize, GEMM_SMEM);
    cudaFuncSetAttribute(mma_gemm<1>, cudaFuncAttributeMaxDynamicSharedMemorySize, GEMM_SMEM);

    // 0) weights -> fp16 scratch
    {
        int total4 = (NDI2 * DM + DM * DI) / 4;
        prep_w<<<(total4 + 255) / 256, 256>>>(W_in, W_out);
    }

    // 1) input LN -> fp16
    ln_kernel<1><<<NTOK, 256>>>(x, ln_in_g, ln_in_b, p_xnorm);

    // 2) GEMM1: [8192 x 3072] = LN(x) @ W_in^T, clip/split/tanh
    {
        dim3 grid(NDI2 / 128, NTOK / 128);
        mma_gemm<0><<<grid, 256, GEMM_SMEM>>>(p_xnorm, p_win, DM, p_xssm, p_gate);
    }

    // 3) scan: fp16(y*tanh(gate)) -> g_y
    scan_kernel<<<(NB * DI) / 128, 128>>>(A_log, Bm, Cm);

    // 4) GEMM2: [8192 x 1024] = y @ W_out^T, clip
    {
        dim3 grid(DM / 128, NTOK / 128);
        mma_gemm<1><<<grid, 256, GEMM_SMEM>>>(p_y, p_wout, DI, p_out1, nullptr);
    }

    // 5) output LN -> fp32 d_out
    ln_kernel<0><<<NTOK, 256>>>(p_out1, ln_out_g, ln_out_b, out);
}

// round 7
// speedup vs baseline: 2.4479x; 1.2590x over previous
#include <cuda_runtime.h>
#include <cuda_fp16.h>
#include <cstdint>

// ---------------------------------------------------------------------------
// SimplifiedMamba2Block on GB300 (sm_103a), compute_103-safe tensor path.
// Round 7: GEMMs are LDGSTS(LSU)-issue bound -> BM=256 x BN=128 tiles
// (1.5x less smem-fill per FLOP), ldmatrix fragment loads, 4-stage ring,
// fp16 intermediates for the scan.
// ---------------------------------------------------------------------------

#define NTOK   8192
#define DM     1024
#define DI     1536
#define DS     8
#define NDI2   3072
#define SEQ    2048
#define NB     4

#define CLIP5(v) fminf(fmaxf((v), -5.0f), 5.0f)

// scratch (__device__ globals per allocation-free rule)
__device__ __half g_xnorm[NTOK * DM];    // LN(x), fp16
__device__ __half g_xh   [NTOK * DI];    // GEMM1 out ssm half, fp16
__device__ __half g_gh   [NTOK * DI];    // GEMM1 out tanh gate, fp16
__device__ __half g_y    [NTOK * DI];    // scan out y*gate, fp16 (GEMM2 A)
__device__ float  g_out1 [NTOK * DM];    // GEMM2 out, fp32
__device__ __half g_win  [NDI2 * DM];    // fp16 W_in
__device__ __half g_wout [DM * DI];      // fp16 W_out

// ======================= helpers ===========================================
__device__ __forceinline__ uint32_t smem_u32(const void* p) {
    uint32_t r;
    asm("{ .reg .u64 t; cvta.to.shared.u64 t, %1; cvt.u32.u64 %0, t; }"
        : "=r"(r) : "l"(p));
    return r;
}
__device__ __forceinline__ void cp_async16(uint32_t saddr, const void* gaddr) {
    asm volatile("cp.async.cg.shared.global [%0], [%1], 16;"
                 :: "r"(saddr), "l"(gaddr) : "memory");
}
#define CP_COMMIT() asm volatile("cp.async.commit_group;" ::: "memory")
#define CP_WAIT(n)  asm volatile("cp.async.wait_group %0;" :: "n"(n) : "memory")

// m16n8k16 f16 MMA (row.col), fp32 accumulate: D += A*B
__device__ __forceinline__ void mma_f16(float* d, const uint32_t* a, const uint32_t* b) {
    asm volatile(
        "mma.sync.aligned.m16n8k16.row.col.f32.f16.f16.f32 "
        "{%0,%1,%2,%3}, {%4,%5,%6,%7}, {%8,%9}, {%0,%1,%2,%3};"
        : "+f"(d[0]), "+f"(d[1]), "+f"(d[2]), "+f"(d[3])
        : "r"(a[0]), "r"(a[1]), "r"(a[2]), "r"(a[3]), "r"(b[0]), "r"(b[1]));
}
__device__ __forceinline__ void ldsm_x4(uint32_t* r, uint32_t addr) {
    asm volatile("ldmatrix.sync.aligned.m8n8.x4.shared.b16 {%0,%1,%2,%3}, [%4];"
                 : "=r"(r[0]), "=r"(r[1]), "=r"(r[2]), "=r"(r[3]) : "r"(addr));
}

// ======================= weight prep (fp32 -> fp16) =========================
__global__ __launch_bounds__(256) void prep_w(
    const float* __restrict__ win, const float* __restrict__ wout)
{
    const int n1 = (NDI2 * DM) / 4;
    const int n2 = (DM * DI) / 4;
    int i = blockIdx.x * blockDim.x + threadIdx.x;
    if (i < n1) {
        float4 v = ((const float4*)win)[i];
        __half2 h0 = __floats2half2_rn(v.x, v.y);
        __half2 h1 = __floats2half2_rn(v.z, v.w);
        uint2 u; u.x = *(uint32_t*)&h0; u.y = *(uint32_t*)&h1;
        ((uint2*)g_win)[i] = u;
    } else if (i < n1 + n2) {
        float4 v = ((const float4*)wout)[i - n1];
        __half2 h0 = __floats2half2_rn(v.x, v.y);
        __half2 h1 = __floats2half2_rn(v.z, v.w);
        uint2 u; u.x = *(uint32_t*)&h0; u.y = *(uint32_t*)&h1;
        ((uint2*)g_wout)[i - n1] = u;
    }
}

// ======================= LayerNorm =========================================
template<int HALF_OUT>
__global__ __launch_bounds__(256) void ln_kernel(
    const float* __restrict__ in, const float* __restrict__ g,
    const float* __restrict__ b, void* __restrict__ outv)
{
    __shared__ float s_sum[8], s_sq[8];
    int row = blockIdx.x;
    int tid = threadIdx.x;
    const float4 v = *(const float4*)(in + (size_t)row * DM + tid * 4);

    float sum = v.x + v.y + v.z + v.w;
    float sq  = v.x*v.x + v.y*v.y + v.z*v.z + v.w*v.w;
    #pragma unroll
    for (int o = 16; o > 0; o >>= 1) {
        sum += __shfl_xor_sync(0xffffffffu, sum, o);
        sq  += __shfl_xor_sync(0xffffffffu, sq , o);
    }
    int wid = tid >> 5, lid = tid & 31;
    if (lid == 0) { s_sum[wid] = sum; s_sq[wid] = sq; }
    __syncthreads();
    if (wid == 0) {
        float a = (lid < 8) ? s_sum[lid] : 0.f;
        float c = (lid < 8) ? s_sq [lid] : 0.f;
        #pragma unroll
        for (int o = 4; o > 0; o >>= 1) {
            a += __shfl_xor_sync(0xffffffffu, a, o);
            c += __shfl_xor_sync(0xffffffffu, c, o);
        }
        if (lid == 0) { s_sum[0] = a; s_sq[0] = c; }
    }
    __syncthreads();
    float mean = s_sum[0] * (1.0f / DM);
    float var  = s_sq[0] * (1.0f / DM) - mean * mean;
    float rstd = rsqrtf(var + 1e-5f);

    const float4 gv = *(const float4*)(g + tid * 4);
    const float4 bv = *(const float4*)(b + tid * 4);
    float4 o4;
    o4.x = (v.x - mean) * rstd * gv.x + bv.x;
    o4.y = (v.y - mean) * rstd * gv.y + bv.y;
    o4.z = (v.z - mean) * rstd * gv.z + bv.z;
    o4.w = (v.w - mean) * rstd * gv.w + bv.w;
    if (HALF_OUT) {
        __half2 h0 = __floats2half2_rn(o4.x, o4.y);
        __half2 h1 = __floats2half2_rn(o4.z, o4.w);
        uint2 u; u.x = *(uint32_t*)&h0; u.y = *(uint32_t*)&h1;
        *(uint2*)((__half*)outv + (size_t)row * DM + tid * 4) = u;
    } else {
        *(float4*)((float*)outv + (size_t)row * DM + tid * 4) = o4;
    }
}

// ======================= mma.sync f16 GEMM (256x128 tile) ===================
// C = A @ W^T. A: MxK rm fp16, W: NxK rm fp16, K % 32 == 0, NC >= 3.
// 256 threads = 8 warps in 4(m) x 2(n); warp tile 64x64 -> acc[4][8][4].
// BK=32. 4-stage cp.async ring (30720 B/stage), one __syncthreads per tile.
// Fragments via ldmatrix.x4. smem row stride 40 halves (80 B) conflict-free.
// MODE 0: clip; bn<DI -> fp16 out0h (x_ssm); else tanh -> fp16 out1h (gate)
// MODE 1: clip -> fp32 out0f
// ---------------------------------------------------------------------------
#define BM      256
#define BN      128
#define STH     40u                 // smem row stride in halves
#define STB     80u                 // ... in bytes
#define A_BYTES (BM * STB)          // 20480
#define W_BYTES (BN * STB)          // 10240
#define STAGEB  (A_BYTES + W_BYTES) // 30720
#define NSTAGE  4
#define GEMM_SMEM (NSTAGE * STAGEB) // 122880

template<int MODE>
__global__ __launch_bounds__(256, 1) void mma_gemm(
    const __half* __restrict__ A, const __half* __restrict__ W, int K,
    __half* __restrict__ out0h, __half* __restrict__ out1h,
    float* __restrict__ out0f)
{
    extern __shared__ __align__(16) char dynsmem[];

    const int tid  = threadIdx.x;
    const int lane = tid & 31;
    const int wid  = tid >> 5;
    const int wm   = wid & 3;          // warp m index (0..3) -> 64 rows
    const int wn   = wid >> 2;         // warp n index (0..1) -> 64 cols
    const int bm   = blockIdx.y * BM;
    const int bn   = blockIdx.x * BN;

    float acc[4][8][4];
    #pragma unroll
    for (int mt = 0; mt < 4; mt++)
        #pragma unroll
        for (int nt = 0; nt < 8; nt++)
            #pragma unroll
            for (int f = 0; f < 4; f++) acc[mt][nt][f] = 0.f;

    // ---- fill addressing: 1024 A ops + 512 W ops per stage, 16 B each ----
    const int frow = tid >> 2;         // 0..63
    const int fseg = tid & 3;          // 16-byte segment of a 64-byte row
    const uint32_t sbase = smem_u32(dynsmem);
    const uint32_t fA = (uint32_t)frow * STB + (uint32_t)fseg * 16u;
    const __half* gA = A + (size_t)(bm + frow) * K + fseg * 8;
    const __half* gW = W + (size_t)(bn + frow) * K + fseg * 8;

    const int NC = K / 32;

    // ---- per-lane ldmatrix offsets ----
    // A (m16k16 as 4 8x8): lanes 0-7 rows0-7@k0, 8-15 rows8-15@k0,
    //                      16-23 rows0-7@k8, 24-31 rows8-15@k8
    const uint32_t laneA = (uint32_t)(lane & 15) * STB + (uint32_t)(lane >> 4) * 16u;
    // B (2 n8k16 tiles):  lanes 0-7 n0-7@k0, 8-15 n0-7@k8,
    //                     16-23 n8-15@k0, 24-31 n8-15@k8
    const uint32_t laneB = (uint32_t)(((lane >> 4) << 3) + (lane & 7)) * STB
                         + (uint32_t)((lane >> 3) & 1) * 16u;

    // ---- prologue: stages 0..2 ----
    #pragma unroll
    for (int t = 0; t < 3; t++) {
        uint32_t base = sbase + t * STAGEB;
        const __half* at = gA + t * 32;
        const __half* wt = gW + t * 32;
        #pragma unroll
        for (int k = 0; k < 4; k++)
            cp_async16(base + fA + k * 64u * STB, at + (size_t)(k * 64) * K);
        #pragma unroll
        for (int k = 0; k < 2; k++)
            cp_async16(base + A_BYTES + fA + k * 64u * STB, wt + (size_t)(k * 64) * K);
        CP_COMMIT();
    }

    for (int c = 0; c < NC; c++) {
        if (c + 3 <= NC)      { CP_WAIT(2); }
        else if (c + 2 == NC) { CP_WAIT(1); }
        else                  { CP_WAIT(0); }
        __syncthreads();               // tile c visible; stage (c-1)%4 free

        if (c + 3 < NC) {              // prefetch tile c+3
            uint32_t base = sbase + ((c + 3) & 3) * STAGEB;
            const __half* at = gA + (c + 3) * 32;
            const __half* wt = gW + (c + 3) * 32;
            #pragma unroll
            for (int k = 0; k < 4; k++)
                cp_async16(base + fA + k * 64u * STB, at + (size_t)(k * 64) * K);
            #pragma unroll
            for (int k = 0; k < 2; k++)
                cp_async16(base + A_BYTES + fA + k * 64u * STB, wt + (size_t)(k * 64) * K);
            CP_COMMIT();
        }

        const uint32_t stA = sbase + (c & 3) * STAGEB;
        const uint32_t stW = stA + A_BYTES;

        #pragma unroll
        for (int ks = 0; ks < 2; ks++) {
            const uint32_t kb = (uint32_t)(ks * 32);   // k0*2 bytes
            uint32_t a[4][4], b[4][4];
            #pragma unroll
            for (int mt = 0; mt < 4; mt++)
                ldsm_x4(a[mt], stA + (uint32_t)(wm * 64 + mt * 16) * STB + kb + laneA);
            #pragma unroll
            for (int np = 0; np < 4; np++)
                ldsm_x4(b[np], stW + (uint32_t)(wn * 64 + np * 16) * STB + kb + laneB);
            #pragma unroll
            for (int mt = 0; mt < 4; mt++)
                #pragma unroll
                for (int nt = 0; nt < 8; nt++)
                    mma_f16(acc[mt][nt], a[mt], &b[nt >> 1][(nt & 1) * 2]);
        }
    }

    // ---- epilogue ----
    #pragma unroll
    for (int mt = 0; mt < 4; mt++) {
        #pragma unroll
        for (int nt = 0; nt < 8; nt++) {
            const int row0 = bm + wm * 64 + mt * 16 + (lane >> 2);
            const int col  = bn + wn * 64 + nt * 8 + (lane & 3) * 2;
            #pragma unroll
            for (int hh = 0; hh < 2; hh++) {
                const int row = row0 + hh * 8;
                float v0 = CLIP5(acc[mt][nt][hh * 2 + 0]);
                float v1 = CLIP5(acc[mt][nt][hh * 2 + 1]);
                if (MODE == 0) {
                    if (col < DI) {
                        __half2 h = __floats2half2_rn(v0, v1);
                        *(__half2*)(out0h + (size_t)row * DI + col) = h;
                    } else {
                        __half2 h = __floats2half2_rn(tanhf(v0), tanhf(v1));
                        *(__half2*)(out1h + (size_t)row * DI + (col - DI)) = h;
                    }
                } else {
                    *(float2*)(out0f + (size_t)row * DM + col) = make_float2(v0, v1);
                }
            }
        }
    }
}

// ======================= SSM scan ===========================================
// One thread per (batch, channel); h in regs; fp16 in (x_ssm, gate) -> fp16
// out (y*gate) in a separate buffer (no aliasing).
// ---------------------------------------------------------------------------
__global__ __launch_bounds__(128) void scan_kernel(
    const float* __restrict__ A_log, const float* __restrict__ Bm,
    const float* __restrict__ Cm)
{
    int idx = blockIdx.x * blockDim.x + threadIdx.x;   // 0..6143
    int b = idx / DI;
    int i = idx - b * DI;

    float decay[DS], bs[DS], cs[DS], hreg[DS];
    #pragma unroll
    for (int s = 0; s < DS; s++) {
        float a = A_log[i * DS + s];
        a = fminf(fmaxf(a, -5.0f), 0.0f);
        float Av = -__expf(a);
        Av = fminf(fmaxf(Av, -2.0f), -0.01f);
        decay[s] = Av * 0.9f;
        bs[s] = Bm[i * DS + s] * 0.1f;
        cs[s] = Cm[i * DS + s];
        hreg[s] = 0.f;
    }

    const __half* __restrict__ xin  = g_xh + (size_t)b * SEQ * DI + i;
    const __half* __restrict__ gin  = g_gh + (size_t)b * SEQ * DI + i;
    __half*       __restrict__ yout = g_y  + (size_t)b * SEQ * DI + i;

    #pragma unroll 8
    for (int t = 0; t < SEQ; t++) {
        float x  = __half2float(xin[(size_t)t * DI]);
        float gt = __half2float(gin[(size_t)t * DI]);
        float y = 0.f;
        #pragma unroll
        for (int s = 0; s < DS; s++) {
            float hs = fmaf(hreg[s], decay[s], x * bs[s]);
            hs = CLIP5(hs);
            hreg[s] = hs;
            y = fmaf(hs, cs[s], y);
        }
        y = CLIP5(y);
        yout[(size_t)t * DI] = __float2half_rn(y * gt);
    }
}

// ======================= launch =============================================
extern "C" void kernel_launch(void* const* d_in, const int* in_sizes, int n_in,
                              void* d_out, int out_size)
{
    const float* x       = (const float*)d_in[0];
    const float* W_in    = (const float*)d_in[1];
    const float* W_out   = (const float*)d_in[2];
    const float* A_log   = (const float*)d_in[3];
    const float* Bm      = (const float*)d_in[4];
    const float* Cm      = (const float*)d_in[5];
    const float* ln_in_g = (const float*)d_in[6];
    const float* ln_in_b = (const float*)d_in[7];
    const float* ln_out_g= (const float*)d_in[8];
    const float* ln_out_b= (const float*)d_in[9];
    float* out = (float*)d_out;

    __half *p_xnorm, *p_xh, *p_gh, *p_y, *p_win, *p_wout;
    float *p_out1;
    cudaGetSymbolAddress((void**)&p_xnorm, g_xnorm);
    cudaGetSymbolAddress((void**)&p_xh   , g_xh);
    cudaGetSymbolAddress((void**)&p_gh   , g_gh);
    cudaGetSymbolAddress((void**)&p_y    , g_y);
    cudaGetSymbolAddress((void**)&p_out1 , g_out1);
    cudaGetSymbolAddress((void**)&p_win  , g_win);
    cudaGetSymbolAddress((void**)&p_wout , g_wout);

    cudaFuncSetAttribute(mma_gemm<0>, cudaFuncAttributeMaxDynamicSharedMemorySize, GEMM_SMEM);
    cudaFuncSetAttribute(mma_gemm<1>, cudaFuncAttributeMaxDynamicSharedMemorySize, GEMM_SMEM);

    // 0) weights -> fp16 scratch
    {
        int total4 = (NDI2 * DM + DM * DI) / 4;
        prep_w<<<(total4 + 255) / 256, 256>>>(W_in, W_out);
    }

    // 1) input LN -> fp16
    ln_kernel<1><<<NTOK, 256>>>(x, ln_in_g, ln_in_b, p_xnorm);

    // 2) GEMM1: [8192 x 3072] = LN(x) @ W_in^T, clip/split/tanh -> fp16
    {
        dim3 grid(NDI2 / BN, NTOK / BM);   // (24, 32)
        mma_gemm<0><<<grid, 256, GEMM_SMEM>>>(p_xnorm, p_win, DM, p_xh, p_gh, nullptr);
    }

    // 3) scan: fp16(y*tanh(gate)) -> g_y
    scan_kernel<<<(NB * DI) / 128, 128>>>(A_log, Bm, Cm);

    // 4) GEMM2: [8192 x 1024] = y @ W_out^T, clip -> fp32
    {
        dim3 grid(DM / BN, NTOK / BM);     // (8, 32)
        mma_gemm<1><<<grid, 256, GEMM_SMEM>>>(p_y, p_wout, DI, nullptr, nullptr, p_out1);
    }

    // 5) output LN -> fp32 d_out
    ln_kernel<0><<<NTOK, 256>>>(p_out1, ln_out_g, ln_out_b, out);
}